// round 12
// baseline (speedup 1.0000x reference)
#include <cuda_runtime.h>
#include <cuda_fp16.h>
#include <cstdint>

#define D_IN   1024
#define D_OUTD 1024
#define NTREES 12
#define NINT   7
#define NCOL   96      // 84 decision cols + 12 gate cols; also 12 trees * 8 leaves
#define NHEADS 3
#define MAX_TOK 8192

// scratch
__device__ __half   g_coefh[MAX_TOK * NCOL];        // [tok][j]  (k2 A operand, fp16)
__device__ uint32_t g_wbfu[2 * NCOL * (D_IN / 2)];  // bf16x2 planes: [hi|lo][96][1024]

__device__ __forceinline__ uint32_t smem_u32(const void* p) {
    uint32_t a;
    asm("{ .reg .u64 t; cvta.to.shared.u64 t, %1; cvt.u32.u64 %0, t; }" : "=r"(a) : "l"(p));
    return a;
}
__device__ __forceinline__ void cpasync16(uint32_t dst, const void* src) {
    asm volatile("cp.async.cg.shared.global [%0], [%1], 16;" :: "r"(dst), "l"(src) : "memory");
}
// split float2 (v.x = even k, v.y = odd k) into bf16x2 hi + bf16x2 residual lo
__device__ __forceinline__ void bsplit(float2 v, uint32_t& hi, uint32_t& lo) {
    asm("cvt.rn.bf16x2.f32 %0, %1, %2;" : "=r"(hi) : "f"(v.y), "f"(v.x));
    float fx = __uint_as_float(hi << 16);
    float fy = __uint_as_float(hi & 0xFFFF0000u);
    asm("cvt.rn.bf16x2.f32 %0, %1, %2;" : "=r"(lo) : "f"(v.y - fy), "f"(v.x - fx));
}

#define MMA_BF16(acc, a, b)                                                     \
    asm("mma.sync.aligned.m16n8k16.row.col.f32.bf16.bf16.f32 "                  \
        "{%0,%1,%2,%3}, {%4,%5,%6,%7}, {%8,%9}, {%0,%1,%2,%3};"                 \
        : "+f"((acc)[0]), "+f"((acc)[1]), "+f"((acc)[2]), "+f"((acc)[3])        \
        : "r"((a)[0]), "r"((a)[1]), "r"((a)[2]), "r"((a)[3]),                   \
          "r"((b)[0]), "r"((b)[1]))

#define MMA_F16(acc, a, b)                                                      \
    asm("mma.sync.aligned.m16n8k16.row.col.f32.f16.f16.f32 "                    \
        "{%0,%1,%2,%3}, {%4,%5,%6,%7}, {%8,%9}, {%0,%1,%2,%3};"                 \
        : "+f"((acc)[0]), "+f"((acc)[1]), "+f"((acc)[2]), "+f"((acc)[3])        \
        : "r"((a)[0]), "r"((a)[1]), "r"((a)[2]), "r"((a)[3]),                   \
          "r"((b)[0]), "r"((b)[1]))

#define LDMX4(r0, r1, r2, r3, addr)                                             \
    asm volatile("ldmatrix.sync.aligned.m8n8.x4.shared.b16 {%0,%1,%2,%3}, [%4];"\
        : "=r"(r0), "=r"(r1), "=r"(r2), "=r"(r3) : "r"(addr))

#define LDMX4T(r0, r1, r2, r3, addr)                                            \
    asm volatile("ldmatrix.sync.aligned.m8n8.x4.trans.shared.b16 "              \
        "{%0,%1,%2,%3}, [%4];"                                                  \
        : "=r"(r0), "=r"(r1), "=r"(r2), "=r"(r3) : "r"(addr))

#define LDMX2(r0, r1, addr)                                                     \
    asm volatile("ldmatrix.sync.aligned.m8n8.x2.shared.b16 {%0,%1}, [%2];"      \
        : "=r"(r0), "=r"(r1) : "r"(addr))

// ---------------------------------------------------------------------------
// Prep kernel (weights only): split routing weights into bf16 hi/lo planes
// ---------------------------------------------------------------------------
__global__ void k_prep(const float* __restrict__ dw, const float* __restrict__ gw)
{
    const int row = blockIdx.x;
    const float* src = (row < 84) ? (dw + (size_t)row * D_IN)
                                  : (gw + (size_t)(row - 84) * D_IN);
    for (int k = threadIdx.x * 4; k < D_IN; k += blockDim.x * 4) {
        float4 v = *(const float4*)&src[k];
        uint32_t h0, l0, h1, l1;
        float2 p0; p0.x = v.x; p0.y = v.y;
        float2 p1; p1.x = v.z; p1.y = v.w;
        bsplit(p0, h0, l0);
        bsplit(p1, h1, l1);
        uint32_t o = (uint32_t)(row * D_IN + k) >> 1;
        g_wbfu[o] = h0;  g_wbfu[o + 1] = h1;
        g_wbfu[NCOL * (D_IN / 2) + o] = l0;  g_wbfu[NCOL * (D_IN / 2) + o + 1] = l1;
    }
}

// ---------------------------------------------------------------------------
// Kernel 1: routing GEMM, bf16x3 split, 512 threads (16 warps: 4m x 4n).
//   Per CTA: 64 tok x 96 col x 1024 K, KC=64 chunks, 2-stage cp.async.
//   Weights from pre-split bf16 planes; x converted in-kernel once/element.
// ---------------------------------------------------------------------------
#define T1     512
#define KC1    64
#define STG1B  46080
#define XH_B   92160
#define XL_B   (92160 + 9216)
#define CST_F  27648
#define SMEM1  (110592 + 768)

__device__ __forceinline__ void k1_stage(uint32_t base, const float* x, int tokbase,
                                          int kb, int tid)
{
#pragma unroll
    for (int i = 0; i < 2; i++) {                 // x: 64 rows x 16 float4
        int idx = i * T1 + tid;
        int row = idx >> 4, c4 = idx & 15;
        cpasync16(base + (uint32_t)(row * 72 + 4 * c4) * 4,
                  &x[(size_t)(tokbase + row) * D_IN + kb + 4 * c4]);
    }
#pragma unroll
    for (int i = 0; i < 3; i++) {                 // w planes: 2 x 96 rows x 8 cp16
        int idx = i * T1 + tid;
        int half_ = idx / 768, rem = idx % 768;
        int row = rem >> 3, q = rem & 7;
        const char* src = (const char*)g_wbfu + (size_t)half_ * (NCOL * D_IN * 2)
                        + (size_t)row * (D_IN * 2) + kb * 2 + q * 16;
        cpasync16(base + 18432u + (uint32_t)half_ * 13824u
                       + (uint32_t)(row * 144 + q * 16), src);
    }
}

__global__ __launch_bounds__(T1, 1) void k1_mma(
    const float* __restrict__ x,
    const float* __restrict__ db,
    const float* __restrict__ ntl,
    const float* __restrict__ gb,
    int ntok)
{
    extern __shared__ float sm[];
    const uint32_t sbase = smem_u32(sm);
    float* sInvT = sm + CST_F;
    float* sBias = sInvT + 84;
    float* sGb   = sBias + 84;

    const int tid = threadIdx.x;
    const int lane = tid & 31, wid = tid >> 5;
    const int m0 = (wid & 3) * 16;      // 4 m-warps x 16 rows
    const int n0 = (wid >> 2) * 24;     // 4 n-warps x 24 cols
    const int tokbase = blockIdx.x * 64;

    const int la_row = (lane & 7) + ((lane >> 3) & 1) * 8;
    const int la_col = (lane >> 4) * 8;
    const int lb_row = (lane & 7) + (lane >> 4) * 8;
    const int lb_col = ((lane >> 3) & 1) * 8;

    if (tid < 84) {
        float z = ntl[tid] + 0.5413f;
        float sp = (z > 15.f) ? z : log1pf(__expf(z));
        sInvT[tid] = 1.0f / sp;
        sBias[tid] = db[tid];
    } else if (tid >= 96 && tid < 96 + NTREES) {
        sGb[tid - 96] = gb[tid - 96];
    }

    float acc[3][4];
#pragma unroll
    for (int tn = 0; tn < 3; tn++)
#pragma unroll
        for (int q = 0; q < 4; q++) acc[tn][q] = 0.f;

    k1_stage(sbase, x, tokbase, 0, tid);
    asm volatile("cp.async.commit_group;" ::: "memory");

    for (int ck = 0; ck < D_IN / KC1; ck++) {
        __syncthreads();
        if (ck < D_IN / KC1 - 1) {
            k1_stage(sbase + ((ck + 1) & 1) * STG1B, x, tokbase, (ck + 1) * KC1, tid);
            asm volatile("cp.async.commit_group;" ::: "memory");
            asm volatile("cp.async.wait_group 1;" ::: "memory");
        } else {
            asm volatile("cp.async.wait_group 0;" ::: "memory");
        }
        __syncthreads();

        // ---- convert x chunk (64x64) to bf16 hi/lo planes, once per element ----
        const float* Xs = sm + (ck & 1) * (STG1B / 4);
#pragma unroll
        for (int i = 0; i < 2; i++) {
            int idx = i * T1 + tid;
            int row = idx >> 4, c4 = idx & 15;
            float4 v = *(const float4*)&Xs[row * 72 + 4 * c4];
            uint32_t h0, l0, h1, l1;
            float2 p0; p0.x = v.x; p0.y = v.y;
            float2 p1; p1.x = v.z; p1.y = v.w;
            bsplit(p0, h0, l0);
            bsplit(p1, h1, l1);
            uint32_t off = (uint32_t)(row * 144 + 8 * c4);
            asm volatile("st.shared.v2.b32 [%0], {%1,%2};"
                         :: "r"(sbase + XH_B + off), "r"(h0), "r"(h1));
            asm volatile("st.shared.v2.b32 [%0], {%1,%2};"
                         :: "r"(sbase + XL_B + off), "r"(l0), "r"(l1));
        }
        __syncthreads();

        const uint32_t whb = sbase + (ck & 1) * STG1B + 18432u;
        const uint32_t wlb = whb + 13824u;

#pragma unroll
        for (int ks = 0; ks < KC1 / 16; ks++) {
            const int kk = ks * 16;
            uint32_t ah[4], al[4], bh[3][2], bl[3][2];
            {
                uint32_t ao = (uint32_t)((m0 + la_row) * 144 + (kk + la_col) * 2);
                LDMX4(ah[0], ah[1], ah[2], ah[3], sbase + XH_B + ao);
                LDMX4(al[0], al[1], al[2], al[3], sbase + XL_B + ao);
            }
#pragma unroll
            for (int tn = 0; tn < 3; tn++) {
                uint32_t bo = (uint32_t)((n0 + tn * 8 + lb_row) * 144 + (kk + lb_col) * 2);
                LDMX2(bh[tn][0], bh[tn][1], whb + bo);
                LDMX2(bl[tn][0], bl[tn][1], wlb + bo);
            }
#pragma unroll
            for (int tn = 0; tn < 3; tn++) {
                MMA_BF16(acc[tn], ah, bh[tn]);
                MMA_BF16(acc[tn], al, bh[tn]);
                MMA_BF16(acc[tn], ah, bl[tn]);
            }
        }
    }

    // ---- logits to smem Ds[64][100], then scalar epilogue ----
    __syncthreads();
    float* Ds = sm;
    {
        const int r = lane >> 2, c = lane & 3;
#pragma unroll
        for (int tn = 0; tn < 3; tn++) {
            float* p = &Ds[(m0 + r) * 100 + n0 + tn * 8 + 2 * c];
            p[0] = acc[tn][0];
            p[1] = acc[tn][1];
            p[8 * 100] = acc[tn][2];
            p[8 * 100 + 1] = acc[tn][3];
        }
    }
    __syncthreads();

    if (tid < 64) {
        const float* d = &Ds[tid * 100];
        float g[NTREES];
        float m = -1e30f;
#pragma unroll
        for (int t = 0; t < NTREES; t++) { g[t] = d[84 + t] + sGb[t]; m = fmaxf(m, g[t]); }
        float s = 0.f;
#pragma unroll
        for (int t = 0; t < NTREES; t++) { g[t] = __expf(g[t] - m); s += g[t]; }
        float inv = 1.0f / s;

        const int tok = tokbase + tid;
        __half2* orow = (__half2*)&g_coefh[(size_t)tok * NCOL];
#pragma unroll
        for (int t = 0; t < NTREES; t++) {
            float w = g[t] * inv;
            float p[NINT];
#pragma unroll
            for (int n = 0; n < NINT; n++) {
                float z = (d[t * 7 + n] + sBias[t * 7 + n]) * sInvT[t * 7 + n];
                p[n] = 1.0f / (1.0f + __expf(-z));
            }
            float a0 = p[0], a1 = 1.f - p[0];
            orow[t * 4 + 0] = __floats2half2_rn(w * a0 * p[1] * p[3],
                                                w * a0 * p[1] * (1.f - p[3]));
            orow[t * 4 + 1] = __floats2half2_rn(w * a0 * (1.f - p[1]) * p[4],
                                                w * a0 * (1.f - p[1]) * (1.f - p[4]));
            orow[t * 4 + 2] = __floats2half2_rn(w * a1 * p[2] * p[5],
                                                w * a1 * p[2] * (1.f - p[5]));
            orow[t * 4 + 3] = __floats2half2_rn(w * a1 * (1.f - p[2]) * p[6],
                                                w * a1 * (1.f - p[2]) * (1.f - p[6]));
        }
    }
}

// ---------------------------------------------------------------------------
// Kernel 2: persistent-B fp16 MMA; B built in-kernel from lo; 2-stage A
//   pipeline; COALESCED epilogue via smem staging (2 halves of 64 rows).
//   Grid (8 d-tiles, 3 heads, 12 s) = 288 CTAs, 2 CTAs/SM.
// smem: B [0, 26112); A0 @26112; A1 @52736; stage(f32) @79360 (33792B).
// ---------------------------------------------------------------------------
#define T2    256
#define SA2   104                       // A row: 104 halfs (208B)
#define SB2   136                       // B row: 136 halfs (272B)
#define B_OFF2   0u
#define A_OFF2   26112u
#define A_STRIDE 26624u
#define STGE_B   79360u
#define STGE_ROW 132                    // floats per stage row (528B)
#define SMEM2    (79360 + 33792)        // 113152 B  (2 CTAs/SM: <=116736)

__device__ __forceinline__ void k2_stageA(uint32_t base, int tokbase, int tid)
{
#pragma unroll
    for (int i = 0; i < 6; i++) {       // 128 rows x 12 cp16
        int idx = i * T2 + tid;
        int row = idx / 12, q = idx % 12;
        cpasync16(base + (uint32_t)(row * SA2 + q * 8) * 2,
                  &g_coefh[(size_t)(tokbase + row) * NCOL + q * 8]);
    }
}

__global__ __launch_bounds__(T2, 2) void k2_mma(
    const float* __restrict__ lo, float* __restrict__ out, int ntok)
{
    extern __shared__ __half smh[];
    const uint32_t sbase = smem_u32(smh);
    float* stage = (float*)(smh + STGE_B / 2);

    const int tid = threadIdx.x;
    const int lane = tid & 31, wid = tid >> 5;
    const int mg = wid >> 2;            // m-warp group (0,1) -> rows mg*64..
    const int m0 = mg * 64;
    const int n0 = (wid & 3) * 32;      // 4 n-warps x 32
    const int dbase = blockIdx.x * 128;
    const int h     = blockIdx.y;
    const int s     = blockIdx.z;       // 0..11
    const int niter = (64 - s + 11) / 12;

    const int la_row = (lane & 7) + ((lane >> 3) & 1) * 8;
    const int la_col = (lane >> 4) * 8;
    const int lbt_row = (lane & 7) + ((lane >> 3) & 1) * 8;
    const int lbt_col = (lane >> 4) * 8;
    const int fr = lane >> 2, fc = lane & 3;

    // A0 prefetch first (flies during B build)
    k2_stageA(sbase + A_OFF2, s * 128, tid);
    asm volatile("cp.async.commit_group;" ::: "memory");

    // build B tile [j][d] fp16 directly from lo (coalesced fp32 rows)
#pragma unroll
    for (int i = 0; i < 12; i++) {
        int idx = i * T2 + tid;        // 96 rows x 32 float4
        int j = idx >> 5, c4 = idx & 31;
        float4 v = *(const float4*)&lo[((size_t)h * NCOL + j) * D_OUTD + dbase + 4 * c4];
        __half2 q0 = __floats2half2_rn(v.x, v.y);
        __half2 q1 = __floats2half2_rn(v.z, v.w);
        asm volatile("st.shared.v2.b32 [%0], {%1,%2};"
                     :: "r"(sbase + (uint32_t)(j * SB2 + 4 * c4) * 2),
                        "r"(*(uint32_t*)&q0), "r"(*(uint32_t*)&q1));
    }

    for (int it = 0; it < niter; it++) {
        // prefetch next A (its buffer was last read in iter it-1; epilogue
        // barriers of iter it-1 make the overwrite safe), then wait for current
        if (it + 1 < niter) {
            k2_stageA(sbase + A_OFF2 + ((it + 1) & 1) * A_STRIDE,
                      (s + 12 * (it + 1)) * 128, tid);
            asm volatile("cp.async.commit_group;" ::: "memory");
            asm volatile("cp.async.wait_group 1;" ::: "memory");
        } else {
            asm volatile("cp.async.wait_group 0;" ::: "memory");
        }
        __syncthreads();

        const uint32_t Ab = sbase + A_OFF2 + (uint32_t)(it & 1) * A_STRIDE;

        float acc[4][4][4];
#pragma unroll
        for (int tm = 0; tm < 4; tm++)
#pragma unroll
            for (int tn = 0; tn < 4; tn++)
#pragma unroll
                for (int q = 0; q < 4; q++) acc[tm][tn][q] = 0.f;

#pragma unroll
        for (int ks = 0; ks < 6; ks++) {
            const int k0h = ks * 16;
            uint32_t a[4][4], b[4][2];
#pragma unroll
            for (int tm = 0; tm < 4; tm++) {
                uint32_t ad = Ab + (uint32_t)((m0 + tm * 16 + la_row) * SA2 + k0h + la_col) * 2;
                LDMX4(a[tm][0], a[tm][1], a[tm][2], a[tm][3], ad);
            }
#pragma unroll
            for (int tp = 0; tp < 2; tp++) {
                uint32_t bd = sbase + B_OFF2 +
                    (uint32_t)((k0h + lbt_row) * SB2 + n0 + tp * 16 + lbt_col) * 2;
                LDMX4T(b[2 * tp][0], b[2 * tp][1], b[2 * tp + 1][0], b[2 * tp + 1][1], bd);
            }
#pragma unroll
            for (int tm = 0; tm < 4; tm++)
#pragma unroll
                for (int tn = 0; tn < 4; tn++)
                    MMA_F16(acc[tm][tn], a[tm], b[tn]);
        }

        // ---- coalesced epilogue via smem stage, 2 halves of 64 rows ----
        const int tokbase = (s + 12 * it) * 128;
#pragma unroll
        for (int hh = 0; hh < 2; hh++) {
            __syncthreads();   // previous half's stage reads complete
#pragma unroll
            for (int tml = 0; tml < 2; tml++) {
                const int tm = 2 * hh + tml;
                const int sr = mg * 32 + tml * 16 + fr;
#pragma unroll
                for (int tn = 0; tn < 4; tn++) {
                    float* p = &stage[sr * STGE_ROW + n0 + tn * 8 + 2 * fc];
                    p[0] = acc[tm][tn][0];
                    p[1] = acc[tm][tn][1];
                    p[8 * STGE_ROW] = acc[tm][tn][2];
                    p[8 * STGE_ROW + 1] = acc[tm][tn][3];
                }
            }
            __syncthreads();
#pragma unroll
            for (int j = 0; j < 8; j++) {
                int lin = j * T2 + tid;
                int sr = lin >> 5, q = lin & 31;
                float4 v = *(const float4*)&stage[sr * STGE_ROW + 4 * q];
                int grow = tokbase + (sr >> 5) * 64 + 32 * hh + (sr & 31);
                *(float4*)&out[((size_t)h * ntok + grow) * D_OUTD + dbase + 4 * q] = v;
            }
        }
    }
}

// ---------------------------------------------------------------------------
extern "C" void kernel_launch(void* const* d_in, const int* in_sizes, int n_in,
                              void* d_out, int out_size)
{
    const float* x   = (const float*)d_in[0];
    const float* dw  = (const float*)d_in[1];
    const float* db  = (const float*)d_in[2];
    const float* ntl = (const float*)d_in[3];
    const float* lo  = (const float*)d_in[4];
    const float* gw  = (const float*)d_in[5];
    const float* gb  = (const float*)d_in[6];
    float* out = (float*)d_out;

    int ntok = in_sizes[0] / D_IN;   // 8192

    cudaFuncSetAttribute(k1_mma, cudaFuncAttributeMaxDynamicSharedMemorySize, SMEM1);
    cudaFuncSetAttribute(k2_mma, cudaFuncAttributeMaxDynamicSharedMemorySize, SMEM2);

    k_prep<<<NCOL, 256>>>(dw, gw);
    k1_mma<<<ntok / 64, T1, SMEM1>>>(x, db, ntl, gb, ntok);

    dim3 g2(D_OUTD / 128, NHEADS, 12);
    k2_mma<<<g2, T2, SMEM2>>>(lo, out, ntok);
}

// round 13
// speedup vs baseline: 1.1459x; 1.1459x over previous
#include <cuda_runtime.h>
#include <cuda_fp16.h>
#include <cstdint>

#define D_IN   1024
#define D_OUTD 1024
#define NTREES 12
#define NINT   7
#define NCOL   96      // 84 decision cols + 12 gate cols; also 12 trees * 8 leaves
#define NHEADS 3
#define MAX_TOK 8192

// scratch
__device__ __half   g_coefh[MAX_TOK * NCOL];        // [tok][j]  (k2 A operand, fp16)
__device__ __half   g_loth[NHEADS * D_OUTD * NCOL]; // [h][d][j] (k2 B operand, fp16)
__device__ uint32_t g_whu[NCOL * (D_IN / 2)];       // fp16x2 weights [96][1024]

__device__ __forceinline__ uint32_t smem_u32(const void* p) {
    uint32_t a;
    asm("{ .reg .u64 t; cvta.to.shared.u64 t, %1; cvt.u32.u64 %0, t; }" : "=r"(a) : "l"(p));
    return a;
}
__device__ __forceinline__ void cpasync16(uint32_t dst, const void* src) {
    asm volatile("cp.async.cg.shared.global [%0], [%1], 16;" :: "r"(dst), "l"(src) : "memory");
}
// split float2 into fp16x2 hi + fp16x2 residual lo
__device__ __forceinline__ void hsplit(float2 v, uint32_t& hi, uint32_t& lo) {
    __half2 h = __floats2half2_rn(v.x, v.y);
    float2 b = __half22float2(h);
    __half2 l = __floats2half2_rn(v.x - b.x, v.y - b.y);
    hi = *(uint32_t*)&h;
    lo = *(uint32_t*)&l;
}

#define MMA_F16(acc, a, b)                                                      \
    asm("mma.sync.aligned.m16n8k16.row.col.f32.f16.f16.f32 "                    \
        "{%0,%1,%2,%3}, {%4,%5,%6,%7}, {%8,%9}, {%0,%1,%2,%3};"                 \
        : "+f"((acc)[0]), "+f"((acc)[1]), "+f"((acc)[2]), "+f"((acc)[3])        \
        : "r"((a)[0]), "r"((a)[1]), "r"((a)[2]), "r"((a)[3]),                   \
          "r"((b)[0]), "r"((b)[1]))

#define LDMX4(r0, r1, r2, r3, addr)                                             \
    asm volatile("ldmatrix.sync.aligned.m8n8.x4.shared.b16 {%0,%1,%2,%3}, [%4];"\
        : "=r"(r0), "=r"(r1), "=r"(r2), "=r"(r3) : "r"(addr))

#define LDMX2(r0, r1, addr)                                                     \
    asm volatile("ldmatrix.sync.aligned.m8n8.x2.shared.b16 {%0,%1}, [%2];"      \
        : "=r"(r0), "=r"(r1) : "r"(addr))

// ---------------------------------------------------------------------------
// Prep kernel: blocks 0..95 convert weights to fp16;
//              blocks 96..383 transpose LO -> fp16 [h][d][j]
// ---------------------------------------------------------------------------
__global__ void k_prep(const float* __restrict__ dw, const float* __restrict__ gw,
                       const float* __restrict__ lo)
{
    const int b = blockIdx.x;
    if (b < NCOL) {
        const int row = b;
        const float* src = (row < 84) ? (dw + (size_t)row * D_IN)
                                      : (gw + (size_t)(row - 84) * D_IN);
        for (int k = threadIdx.x * 4; k < D_IN; k += blockDim.x * 4) {
            float4 v = *(const float4*)&src[k];
            __half2 h0 = __floats2half2_rn(v.x, v.y);
            __half2 h1 = __floats2half2_rn(v.z, v.w);
            uint32_t o = (uint32_t)(row * D_IN + k) >> 1;
            g_whu[o] = *(uint32_t*)&h0;
            g_whu[o + 1] = *(uint32_t*)&h1;
        }
    } else {
        __shared__ float t[32][33];
        const int tt = b - NCOL;                    // 0..287
        const int d0 = (tt & 31) * 32;
        const int j0 = ((tt >> 5) % 3) * 32;
        const int h  = tt / 96;
        const int tx = threadIdx.x & 31, ty = threadIdx.x >> 5;  // 32 x 8
#pragma unroll
        for (int i = 0; i < 32; i += 8)
            t[ty + i][tx] = lo[((size_t)h * NCOL + (j0 + ty + i)) * D_OUTD + d0 + tx];
        __syncthreads();
#pragma unroll
        for (int i = 0; i < 32; i += 8)
            g_loth[((size_t)h * D_OUTD + (d0 + ty + i)) * NCOL + j0 + tx] =
                __float2half_rn(t[tx][ty + i]);
    }
}

// ---------------------------------------------------------------------------
// Kernel 1: routing GEMM, fp16x2 split (x hi+lo, w single fp16).
//   512 threads (16 warps: 4m x 4n), 64 tok x 96 col x 1024 K, KC=64,
//   2-stage cp.async.  2 MMAs per k16 (was 3).
// smem bytes per stage (32256): Xraw 64x72 f32 [0,18432); W fp16 96x72 halfs
//   [18432,32256).  Planes: Xh@64512 (64x144B), Xl@73728.  consts@82944.
//   Ds epilogue overlay @0 (64x100 f32).
// ---------------------------------------------------------------------------
#define T1     512
#define KC1    64
#define STG1B  32256
#define XH_B   64512u
#define XL_B   73728u
#define CST_F  20736
#define SMEM1  (82944 + 768)

__device__ __forceinline__ void k1_stage(uint32_t base, const float* x, int tokbase,
                                          int kb, int tid)
{
#pragma unroll
    for (int i = 0; i < 2; i++) {                 // x raw: 64 rows x 16 float4
        int idx = i * T1 + tid;
        int row = idx >> 4, c4 = idx & 15;
        cpasync16(base + (uint32_t)(row * 72 + 4 * c4) * 4,
                  &x[(size_t)(tokbase + row) * D_IN + kb + 4 * c4]);
    }
#pragma unroll
    for (int i = 0; i < 2; i++) {                 // w fp16: 96 rows x 8 cp16
        int idx = i * T1 + tid;
        if (idx < 768) {
            int row = idx >> 3, q = idx & 7;
            const char* src = (const char*)g_whu + (size_t)row * (D_IN * 2)
                            + kb * 2 + q * 16;
            cpasync16(base + 18432u + (uint32_t)(row * 144 + q * 16), src);
        }
    }
}

__global__ __launch_bounds__(T1, 1) void k1_mma(
    const float* __restrict__ x,
    const float* __restrict__ db,
    const float* __restrict__ ntl,
    const float* __restrict__ gb,
    int ntok)
{
    extern __shared__ float sm[];
    const uint32_t sbase = smem_u32(sm);
    float* sInvT = sm + CST_F;
    float* sBias = sInvT + 84;
    float* sGb   = sBias + 84;

    const int tid = threadIdx.x;
    const int lane = tid & 31, wid = tid >> 5;
    const int m0 = (wid & 3) * 16;      // 4 m-warps x 16 rows
    const int n0 = (wid >> 2) * 24;     // 4 n-warps x 24 cols
    const int tokbase = blockIdx.x * 64;

    const int la_row = (lane & 7) + ((lane >> 3) & 1) * 8;
    const int la_col = (lane >> 4) * 8;
    const int lb_row = (lane & 7) + (lane >> 4) * 8;
    const int lb_col = ((lane >> 3) & 1) * 8;

    if (tid < 84) {
        float z = ntl[tid] + 0.5413f;
        float sp = (z > 15.f) ? z : log1pf(__expf(z));
        sInvT[tid] = 1.0f / sp;
        sBias[tid] = db[tid];
    } else if (tid >= 96 && tid < 96 + NTREES) {
        sGb[tid - 96] = gb[tid - 96];
    }

    float acc[3][4];
#pragma unroll
    for (int tn = 0; tn < 3; tn++)
#pragma unroll
        for (int q = 0; q < 4; q++) acc[tn][q] = 0.f;

    k1_stage(sbase, x, tokbase, 0, tid);
    asm volatile("cp.async.commit_group;" ::: "memory");

    for (int ck = 0; ck < D_IN / KC1; ck++) {
        __syncthreads();
        if (ck < D_IN / KC1 - 1) {
            k1_stage(sbase + ((ck + 1) & 1) * STG1B, x, tokbase, (ck + 1) * KC1, tid);
            asm volatile("cp.async.commit_group;" ::: "memory");
            asm volatile("cp.async.wait_group 1;" ::: "memory");
        } else {
            asm volatile("cp.async.wait_group 0;" ::: "memory");
        }
        __syncthreads();

        // ---- split x chunk (64x64) into fp16 hi/lo planes, once per element ----
        const float* Xs = sm + (ck & 1) * (STG1B / 4);
#pragma unroll
        for (int i = 0; i < 2; i++) {
            int idx = i * T1 + tid;
            int row = idx >> 4, c4 = idx & 15;
            float4 v = *(const float4*)&Xs[row * 72 + 4 * c4];
            uint32_t h0, l0, h1, l1;
            float2 p0; p0.x = v.x; p0.y = v.y;
            float2 p1; p1.x = v.z; p1.y = v.w;
            hsplit(p0, h0, l0);
            hsplit(p1, h1, l1);
            uint32_t off = (uint32_t)(row * 144 + 8 * c4);
            asm volatile("st.shared.v2.b32 [%0], {%1,%2};"
                         :: "r"(sbase + XH_B + off), "r"(h0), "r"(h1));
            asm volatile("st.shared.v2.b32 [%0], {%1,%2};"
                         :: "r"(sbase + XL_B + off), "r"(l0), "r"(l1));
        }
        __syncthreads();

        const uint32_t wb = sbase + (ck & 1) * STG1B + 18432u;

#pragma unroll
        for (int ks = 0; ks < KC1 / 16; ks++) {
            const int kk = ks * 16;
            uint32_t ah[4], al[4], bh[3][2];
            {
                uint32_t ao = (uint32_t)((m0 + la_row) * 144 + (kk + la_col) * 2);
                LDMX4(ah[0], ah[1], ah[2], ah[3], sbase + XH_B + ao);
                LDMX4(al[0], al[1], al[2], al[3], sbase + XL_B + ao);
            }
#pragma unroll
            for (int tn = 0; tn < 3; tn++) {
                uint32_t bo = (uint32_t)((n0 + tn * 8 + lb_row) * 144 + (kk + lb_col) * 2);
                LDMX2(bh[tn][0], bh[tn][1], wb + bo);
            }
#pragma unroll
            for (int tn = 0; tn < 3; tn++) {
                MMA_F16(acc[tn], ah, bh[tn]);
                MMA_F16(acc[tn], al, bh[tn]);
            }
        }
    }

    // ---- logits to smem Ds[64][100], then scalar epilogue ----
    __syncthreads();
    float* Ds = sm;
    {
        const int r = lane >> 2, c = lane & 3;
#pragma unroll
        for (int tn = 0; tn < 3; tn++) {
            float* p = &Ds[(m0 + r) * 100 + n0 + tn * 8 + 2 * c];
            p[0] = acc[tn][0];
            p[1] = acc[tn][1];
            p[8 * 100] = acc[tn][2];
            p[8 * 100 + 1] = acc[tn][3];
        }
    }
    __syncthreads();

    if (tid < 64) {
        const float* d = &Ds[tid * 100];
        float g[NTREES];
        float m = -1e30f;
#pragma unroll
        for (int t = 0; t < NTREES; t++) { g[t] = d[84 + t] + sGb[t]; m = fmaxf(m, g[t]); }
        float s = 0.f;
#pragma unroll
        for (int t = 0; t < NTREES; t++) { g[t] = __expf(g[t] - m); s += g[t]; }
        float inv = 1.0f / s;

        const int tok = tokbase + tid;
        __half2* orow = (__half2*)&g_coefh[(size_t)tok * NCOL];
#pragma unroll
        for (int t = 0; t < NTREES; t++) {
            float w = g[t] * inv;
            float p[NINT];
#pragma unroll
            for (int n = 0; n < NINT; n++) {
                float z = (d[t * 7 + n] + sBias[t * 7 + n]) * sInvT[t * 7 + n];
                p[n] = 1.0f / (1.0f + __expf(-z));
            }
            float a0 = p[0], a1 = 1.f - p[0];
            orow[t * 4 + 0] = __floats2half2_rn(w * a0 * p[1] * p[3],
                                                w * a0 * p[1] * (1.f - p[3]));
            orow[t * 4 + 1] = __floats2half2_rn(w * a0 * (1.f - p[1]) * p[4],
                                                w * a0 * (1.f - p[1]) * (1.f - p[4]));
            orow[t * 4 + 2] = __floats2half2_rn(w * a1 * p[2] * p[5],
                                                w * a1 * p[2] * (1.f - p[5]));
            orow[t * 4 + 3] = __floats2half2_rn(w * a1 * (1.f - p[2]) * p[6],
                                                w * a1 * (1.f - p[2]) * (1.f - p[6]));
        }
    }
}

// ---------------------------------------------------------------------------
// Kernel 2: persistent-B fp16 MMA, ldmatrix, 3-stage A pipeline,
//   SINGLE __syncthreads per iteration (wait -> sync -> issue it+2 -> compute).
//   Grid (8 d-tiles, 3 heads, 12 s) = 288 CTAs, 2 CTAs/SM.  (R10 verbatim)
// ---------------------------------------------------------------------------
#define T2    256
#define SA2   104                      // halfs per smem row (208B, conflict-free)
#define BS2H  (128 * SA2)              // 13312 halfs
#define AS2H  (128 * SA2)
#define SMEM2 ((BS2H + 3 * AS2H) * 2)  // 106496 B

__device__ __forceinline__ void k2_stageA(uint32_t base, int tokbase, int tid)
{
#pragma unroll
    for (int i = 0; i < 6; i++) {      // 128 rows x 12 cp16
        int idx = i * T2 + tid;
        int row = idx / 12, q = idx % 12;
        cpasync16(base + (uint32_t)(row * SA2 + q * 8) * 2,
                  &g_coefh[(size_t)(tokbase + row) * NCOL + q * 8]);
    }
}

__global__ __launch_bounds__(T2, 2) void k2_mma(float* __restrict__ out, int ntok)
{
    extern __shared__ __half smh[];
    const uint32_t sbase = smem_u32(smh);

    const int tid = threadIdx.x;
    const int lane = tid & 31, wid = tid >> 5;
    const int m0 = (wid >> 2) * 64;    // 2 m-warps x 64
    const int n0 = (wid & 3) * 32;     // 4 n-warps x 32
    const int dbase = blockIdx.x * 128;
    const int h     = blockIdx.y;
    const int s     = blockIdx.z;      // 0..11
    const int niter = (64 - s + 11) / 12;

    const int la_row = (lane & 7) + ((lane >> 3) & 1) * 8;
    const int la_col = (lane >> 4) * 8;
    const int lb_row = (lane & 7) + (lane >> 4) * 8;
    const int lb_col = ((lane >> 3) & 1) * 8;

    // stage B + A0 (group 0); A1 (group 1)
#pragma unroll
    for (int i = 0; i < 6; i++) {
        int idx = i * T2 + tid;
        int row = idx / 12, q = idx % 12;
        cpasync16(sbase + (uint32_t)(row * SA2 + q * 8) * 2,
                  &g_loth[((size_t)h * D_OUTD + dbase + row) * NCOL + q * 8]);
    }
    k2_stageA(sbase + BS2H * 2, s * 128, tid);
    asm volatile("cp.async.commit_group;" ::: "memory");
    if (1 < niter) {
        k2_stageA(sbase + (BS2H + AS2H) * 2, (s + 12) * 128, tid);
        asm volatile("cp.async.commit_group;" ::: "memory");
    }

    for (int it = 0; it < niter; it++) {
        if (it + 1 < niter) {
            asm volatile("cp.async.wait_group 1;" ::: "memory");
        } else {
            asm volatile("cp.async.wait_group 0;" ::: "memory");
        }
        __syncthreads();
        if (it + 2 < niter) {
            k2_stageA(sbase + (BS2H + ((it + 2) % 3) * AS2H) * 2,
                      (s + 12 * (it + 2)) * 128, tid);
            asm volatile("cp.async.commit_group;" ::: "memory");
        }

        const uint32_t Ab = sbase + (uint32_t)(BS2H + (it % 3) * AS2H) * 2;

        float acc[4][4][4];
#pragma unroll
        for (int tm = 0; tm < 4; tm++)
#pragma unroll
            for (int tn = 0; tn < 4; tn++)
#pragma unroll
                for (int q = 0; q < 4; q++) acc[tm][tn][q] = 0.f;

#pragma unroll
        for (int ks = 0; ks < 6; ks++) {
            const int k0h = ks * 16;
            uint32_t a[4][4], b[4][2];
#pragma unroll
            for (int tm = 0; tm < 4; tm++) {
                uint32_t ad = Ab + (uint32_t)((m0 + tm * 16 + la_row) * SA2 + k0h + la_col) * 2;
                LDMX4(a[tm][0], a[tm][1], a[tm][2], a[tm][3], ad);
            }
#pragma unroll
            for (int tp = 0; tp < 2; tp++) {
                uint32_t bd = sbase + (uint32_t)((n0 + tp * 16 + lb_row) * SA2 + k0h + lb_col) * 2;
                LDMX4(b[2 * tp][0], b[2 * tp][1], b[2 * tp + 1][0], b[2 * tp + 1][1], bd);
            }
#pragma unroll
            for (int tm = 0; tm < 4; tm++)
#pragma unroll
                for (int tn = 0; tn < 4; tn++)
                    MMA_F16(acc[tm][tn], a[tm], b[tn]);
        }

        // epilogue
        const int tokbase = (s + 12 * it) * 128;
#pragma unroll
        for (int tm = 0; tm < 4; tm++) {
            const size_t row0 = (size_t)tokbase + m0 + tm * 16 + (lane >> 2);
            float* ob = out + ((size_t)h * ntok + row0) * D_OUTD + dbase + n0 + 2 * (lane & 3);
#pragma unroll
            for (int tn = 0; tn < 4; tn++) {
                float2 v0; v0.x = acc[tm][tn][0]; v0.y = acc[tm][tn][1];
                float2 v1; v1.x = acc[tm][tn][2]; v1.y = acc[tm][tn][3];
                *(float2*)(ob + tn * 8) = v0;
                *(float2*)(ob + tn * 8 + 8 * D_OUTD) = v1;
            }
        }
    }
}

// ---------------------------------------------------------------------------
extern "C" void kernel_launch(void* const* d_in, const int* in_sizes, int n_in,
                              void* d_out, int out_size)
{
    const float* x   = (const float*)d_in[0];
    const float* dw  = (const float*)d_in[1];
    const float* db  = (const float*)d_in[2];
    const float* ntl = (const float*)d_in[3];
    const float* lo  = (const float*)d_in[4];
    const float* gw  = (const float*)d_in[5];
    const float* gb  = (const float*)d_in[6];
    float* out = (float*)d_out;

    int ntok = in_sizes[0] / D_IN;   // 8192

    cudaFuncSetAttribute(k1_mma, cudaFuncAttributeMaxDynamicSharedMemorySize, SMEM1);
    cudaFuncSetAttribute(k2_mma, cudaFuncAttributeMaxDynamicSharedMemorySize, SMEM2);

    k_prep<<<NCOL + 288, 256>>>(dw, gw, lo);
    k1_mma<<<ntok / 64, T1, SMEM1>>>(x, db, ntl, gb, ntok);

    dim3 g2(D_OUTD / 128, NHEADS, 12);
    k2_mma<<<g2, T2, SMEM2>>>(out, ntok);
}

// round 14
// speedup vs baseline: 1.2301x; 1.0734x over previous
#include <cuda_runtime.h>
#include <cuda_fp16.h>
#include <cstdint>

#define D_IN   1024
#define D_OUTD 1024
#define NTREES 12
#define NINT   7
#define NCOL   96      // 84 decision cols + 12 gate cols; also 12 trees * 8 leaves
#define NHEADS 3
#define MAX_TOK 8192

// scratch
__device__ __half   g_coefh[MAX_TOK * NCOL];        // [tok][j]  (k2 A operand, fp16)
__device__ __half   g_loth[NHEADS * D_OUTD * NCOL]; // [h][d][j] (k2 B operand, fp16)
__device__ uint32_t g_whu[NCOL * (D_IN / 2)];       // fp16x2 weights [96][1024]

__device__ __forceinline__ uint32_t smem_u32(const void* p) {
    uint32_t a;
    asm("{ .reg .u64 t; cvta.to.shared.u64 t, %1; cvt.u32.u64 %0, t; }" : "=r"(a) : "l"(p));
    return a;
}
__device__ __forceinline__ void cpasync16(uint32_t dst, const void* src) {
    asm volatile("cp.async.cg.shared.global [%0], [%1], 16;" :: "r"(dst), "l"(src) : "memory");
}

#define MMA_F16(acc, a, b)                                                      \
    asm("mma.sync.aligned.m16n8k16.row.col.f32.f16.f16.f32 "                    \
        "{%0,%1,%2,%3}, {%4,%5,%6,%7}, {%8,%9}, {%0,%1,%2,%3};"                 \
        : "+f"((acc)[0]), "+f"((acc)[1]), "+f"((acc)[2]), "+f"((acc)[3])        \
        : "r"((a)[0]), "r"((a)[1]), "r"((a)[2]), "r"((a)[3]),                   \
          "r"((b)[0]), "r"((b)[1]))

#define LDMX4(r0, r1, r2, r3, addr)                                             \
    asm volatile("ldmatrix.sync.aligned.m8n8.x4.shared.b16 {%0,%1,%2,%3}, [%4];"\
        : "=r"(r0), "=r"(r1), "=r"(r2), "=r"(r3) : "r"(addr))

#define LDMX2(r0, r1, addr)                                                     \
    asm volatile("ldmatrix.sync.aligned.m8n8.x2.shared.b16 {%0,%1}, [%2];"      \
        : "=r"(r0), "=r"(r1) : "r"(addr))

// ---------------------------------------------------------------------------
// Prep kernel: blocks 0..95 convert weights to fp16;
//              blocks 96..383 transpose LO -> fp16 [h][d][j]
// ---------------------------------------------------------------------------
__global__ void k_prep(const float* __restrict__ dw, const float* __restrict__ gw,
                       const float* __restrict__ lo)
{
    const int b = blockIdx.x;
    if (b < NCOL) {
        const int row = b;
        const float* src = (row < 84) ? (dw + (size_t)row * D_IN)
                                      : (gw + (size_t)(row - 84) * D_IN);
        for (int k = threadIdx.x * 4; k < D_IN; k += blockDim.x * 4) {
            float4 v = *(const float4*)&src[k];
            __half2 h0 = __floats2half2_rn(v.x, v.y);
            __half2 h1 = __floats2half2_rn(v.z, v.w);
            uint32_t o = (uint32_t)(row * D_IN + k) >> 1;
            g_whu[o] = *(uint32_t*)&h0;
            g_whu[o + 1] = *(uint32_t*)&h1;
        }
    } else {
        __shared__ float t[32][33];
        const int tt = b - NCOL;                    // 0..287
        const int d0 = (tt & 31) * 32;
        const int j0 = ((tt >> 5) % 3) * 32;
        const int h  = tt / 96;
        const int tx = threadIdx.x & 31, ty = threadIdx.x >> 5;  // 32 x 8
#pragma unroll
        for (int i = 0; i < 32; i += 8)
            t[ty + i][tx] = lo[((size_t)h * NCOL + (j0 + ty + i)) * D_OUTD + d0 + tx];
        __syncthreads();
#pragma unroll
        for (int i = 0; i < 32; i += 8)
            g_loth[((size_t)h * D_OUTD + (d0 + ty + i)) * NCOL + j0 + tx] =
                __float2half_rn(t[tx][ty + i]);
    }
}

// ---------------------------------------------------------------------------
// Kernel 1: routing GEMM, single fp16 both operands (1 MMA per k16).
//   512 threads (16 warps: 4m x 4n), 64 tok x 96 col x 1024 K, KC=64,
//   2-stage cp.async.
// smem bytes per stage (32256): Xraw 64x72 f32 [0,18432); W fp16 96x72 halfs
//   [18432,32256).  Xh plane @64512 (64x144B = 9216).  consts @73728.
//   Ds epilogue overlay @0 (64x100 f32).
// ---------------------------------------------------------------------------
#define T1     512
#define KC1    64
#define STG1B  32256
#define XH_B   64512u
#define CST_F  18432
#define SMEM1  (73728 + 768)

__device__ __forceinline__ void k1_stage(uint32_t base, const float* x, int tokbase,
                                          int kb, int tid)
{
#pragma unroll
    for (int i = 0; i < 2; i++) {                 // x raw: 64 rows x 16 float4
        int idx = i * T1 + tid;
        int row = idx >> 4, c4 = idx & 15;
        cpasync16(base + (uint32_t)(row * 72 + 4 * c4) * 4,
                  &x[(size_t)(tokbase + row) * D_IN + kb + 4 * c4]);
    }
#pragma unroll
    for (int i = 0; i < 2; i++) {                 // w fp16: 96 rows x 8 cp16
        int idx = i * T1 + tid;
        if (idx < 768) {
            int row = idx >> 3, q = idx & 7;
            const char* src = (const char*)g_whu + (size_t)row * (D_IN * 2)
                            + kb * 2 + q * 16;
            cpasync16(base + 18432u + (uint32_t)(row * 144 + q * 16), src);
        }
    }
}

__global__ __launch_bounds__(T1, 1) void k1_mma(
    const float* __restrict__ x,
    const float* __restrict__ db,
    const float* __restrict__ ntl,
    const float* __restrict__ gb,
    int ntok)
{
    extern __shared__ float sm[];
    const uint32_t sbase = smem_u32(sm);
    float* sInvT = sm + CST_F;
    float* sBias = sInvT + 84;
    float* sGb   = sBias + 84;

    const int tid = threadIdx.x;
    const int lane = tid & 31, wid = tid >> 5;
    const int m0 = (wid & 3) * 16;      // 4 m-warps x 16 rows
    const int n0 = (wid >> 2) * 24;     // 4 n-warps x 24 cols
    const int tokbase = blockIdx.x * 64;

    const int la_row = (lane & 7) + ((lane >> 3) & 1) * 8;
    const int la_col = (lane >> 4) * 8;
    const int lb_row = (lane & 7) + (lane >> 4) * 8;
    const int lb_col = ((lane >> 3) & 1) * 8;

    if (tid < 84) {
        float z = ntl[tid] + 0.5413f;
        float sp = (z > 15.f) ? z : log1pf(__expf(z));
        sInvT[tid] = 1.0f / sp;
        sBias[tid] = db[tid];
    } else if (tid >= 96 && tid < 96 + NTREES) {
        sGb[tid - 96] = gb[tid - 96];
    }

    float acc[3][4];
#pragma unroll
    for (int tn = 0; tn < 3; tn++)
#pragma unroll
        for (int q = 0; q < 4; q++) acc[tn][q] = 0.f;

    k1_stage(sbase, x, tokbase, 0, tid);
    asm volatile("cp.async.commit_group;" ::: "memory");

    for (int ck = 0; ck < D_IN / KC1; ck++) {
        __syncthreads();
        if (ck < D_IN / KC1 - 1) {
            k1_stage(sbase + ((ck + 1) & 1) * STG1B, x, tokbase, (ck + 1) * KC1, tid);
            asm volatile("cp.async.commit_group;" ::: "memory");
            asm volatile("cp.async.wait_group 1;" ::: "memory");
        } else {
            asm volatile("cp.async.wait_group 0;" ::: "memory");
        }
        __syncthreads();

        // ---- convert x chunk (64x64) to ONE fp16 plane, once per element ----
        const float* Xs = sm + (ck & 1) * (STG1B / 4);
#pragma unroll
        for (int i = 0; i < 2; i++) {
            int idx = i * T1 + tid;
            int row = idx >> 4, c4 = idx & 15;
            float4 v = *(const float4*)&Xs[row * 72 + 4 * c4];
            __half2 h0 = __floats2half2_rn(v.x, v.y);
            __half2 h1 = __floats2half2_rn(v.z, v.w);
            uint32_t off = (uint32_t)(row * 144 + 8 * c4);
            asm volatile("st.shared.v2.b32 [%0], {%1,%2};"
                         :: "r"(sbase + XH_B + off),
                            "r"(*(uint32_t*)&h0), "r"(*(uint32_t*)&h1));
        }
        __syncthreads();

        const uint32_t wb = sbase + (ck & 1) * STG1B + 18432u;

#pragma unroll
        for (int ks = 0; ks < KC1 / 16; ks++) {
            const int kk = ks * 16;
            uint32_t ah[4], bh[3][2];
            {
                uint32_t ao = (uint32_t)((m0 + la_row) * 144 + (kk + la_col) * 2);
                LDMX4(ah[0], ah[1], ah[2], ah[3], sbase + XH_B + ao);
            }
#pragma unroll
            for (int tn = 0; tn < 3; tn++) {
                uint32_t bo = (uint32_t)((n0 + tn * 8 + lb_row) * 144 + (kk + lb_col) * 2);
                LDMX2(bh[tn][0], bh[tn][1], wb + bo);
            }
#pragma unroll
            for (int tn = 0; tn < 3; tn++)
                MMA_F16(acc[tn], ah, bh[tn]);
        }
    }

    // ---- logits to smem Ds[64][100], then scalar epilogue ----
    __syncthreads();
    float* Ds = sm;
    {
        const int r = lane >> 2, c = lane & 3;
#pragma unroll
        for (int tn = 0; tn < 3; tn++) {
            float* p = &Ds[(m0 + r) * 100 + n0 + tn * 8 + 2 * c];
            p[0] = acc[tn][0];
            p[1] = acc[tn][1];
            p[8 * 100] = acc[tn][2];
            p[8 * 100 + 1] = acc[tn][3];
        }
    }
    __syncthreads();

    if (tid < 64) {
        const float* d = &Ds[tid * 100];
        float g[NTREES];
        float m = -1e30f;
#pragma unroll
        for (int t = 0; t < NTREES; t++) { g[t] = d[84 + t] + sGb[t]; m = fmaxf(m, g[t]); }
        float s = 0.f;
#pragma unroll
        for (int t = 0; t < NTREES; t++) { g[t] = __expf(g[t] - m); s += g[t]; }
        float inv = 1.0f / s;

        const int tok = tokbase + tid;
        __half2* orow = (__half2*)&g_coefh[(size_t)tok * NCOL];
#pragma unroll
        for (int t = 0; t < NTREES; t++) {
            float w = g[t] * inv;
            float p[NINT];
#pragma unroll
            for (int n = 0; n < NINT; n++) {
                float z = (d[t * 7 + n] + sBias[t * 7 + n]) * sInvT[t * 7 + n];
                p[n] = 1.0f / (1.0f + __expf(-z));
            }
            float a0 = p[0], a1 = 1.f - p[0];
            orow[t * 4 + 0] = __floats2half2_rn(w * a0 * p[1] * p[3],
                                                w * a0 * p[1] * (1.f - p[3]));
            orow[t * 4 + 1] = __floats2half2_rn(w * a0 * (1.f - p[1]) * p[4],
                                                w * a0 * (1.f - p[1]) * (1.f - p[4]));
            orow[t * 4 + 2] = __floats2half2_rn(w * a1 * p[2] * p[5],
                                                w * a1 * p[2] * (1.f - p[5]));
            orow[t * 4 + 3] = __floats2half2_rn(w * a1 * (1.f - p[2]) * p[6],
                                                w * a1 * (1.f - p[2]) * (1.f - p[6]));
        }
    }
}

// ---------------------------------------------------------------------------
// Kernel 2: persistent-B fp16 MMA, ldmatrix, 3-stage A pipeline,
//   SINGLE __syncthreads per iteration (wait -> sync -> issue it+2 -> compute).
//   Grid (8 d-tiles, 3 heads, 12 s) = 288 CTAs, 2 CTAs/SM.  (R13 verbatim)
// ---------------------------------------------------------------------------
#define T2    256
#define SA2   104                      // halfs per smem row (208B, conflict-free)
#define BS2H  (128 * SA2)              // 13312 halfs
#define AS2H  (128 * SA2)
#define SMEM2 ((BS2H + 3 * AS2H) * 2)  // 106496 B

__device__ __forceinline__ void k2_stageA(uint32_t base, int tokbase, int tid)
{
#pragma unroll
    for (int i = 0; i < 6; i++) {      // 128 rows x 12 cp16
        int idx = i * T2 + tid;
        int row = idx / 12, q = idx % 12;
        cpasync16(base + (uint32_t)(row * SA2 + q * 8) * 2,
                  &g_coefh[(size_t)(tokbase + row) * NCOL + q * 8]);
    }
}

__global__ __launch_bounds__(T2, 2) void k2_mma(float* __restrict__ out, int ntok)
{
    extern __shared__ __half smh[];
    const uint32_t sbase = smem_u32(smh);

    const int tid = threadIdx.x;
    const int lane = tid & 31, wid = tid >> 5;
    const int m0 = (wid >> 2) * 64;    // 2 m-warps x 64
    const int n0 = (wid & 3) * 32;     // 4 n-warps x 32
    const int dbase = blockIdx.x * 128;
    const int h     = blockIdx.y;
    const int s     = blockIdx.z;      // 0..11
    const int niter = (64 - s + 11) / 12;

    const int la_row = (lane & 7) + ((lane >> 3) & 1) * 8;
    const int la_col = (lane >> 4) * 8;
    const int lb_row = (lane & 7) + (lane >> 4) * 8;
    const int lb_col = ((lane >> 3) & 1) * 8;

    // stage B + A0 (group 0); A1 (group 1)
#pragma unroll
    for (int i = 0; i < 6; i++) {
        int idx = i * T2 + tid;
        int row = idx / 12, q = idx % 12;
        cpasync16(sbase + (uint32_t)(row * SA2 + q * 8) * 2,
                  &g_loth[((size_t)h * D_OUTD + dbase + row) * NCOL + q * 8]);
    }
    k2_stageA(sbase + BS2H * 2, s * 128, tid);
    asm volatile("cp.async.commit_group;" ::: "memory");
    if (1 < niter) {
        k2_stageA(sbase + (BS2H + AS2H) * 2, (s + 12) * 128, tid);
        asm volatile("cp.async.commit_group;" ::: "memory");
    }

    for (int it = 0; it < niter; it++) {
        if (it + 1 < niter) {
            asm volatile("cp.async.wait_group 1;" ::: "memory");
        } else {
            asm volatile("cp.async.wait_group 0;" ::: "memory");
        }
        __syncthreads();
        if (it + 2 < niter) {
            k2_stageA(sbase + (BS2H + ((it + 2) % 3) * AS2H) * 2,
                      (s + 12 * (it + 2)) * 128, tid);
            asm volatile("cp.async.commit_group;" ::: "memory");
        }

        const uint32_t Ab = sbase + (uint32_t)(BS2H + (it % 3) * AS2H) * 2;

        float acc[4][4][4];
#pragma unroll
        for (int tm = 0; tm < 4; tm++)
#pragma unroll
            for (int tn = 0; tn < 4; tn++)
#pragma unroll
                for (int q = 0; q < 4; q++) acc[tm][tn][q] = 0.f;

#pragma unroll
        for (int ks = 0; ks < 6; ks++) {
            const int k0h = ks * 16;
            uint32_t a[4][4], b[4][2];
#pragma unroll
            for (int tm = 0; tm < 4; tm++) {
                uint32_t ad = Ab + (uint32_t)((m0 + tm * 16 + la_row) * SA2 + k0h + la_col) * 2;
                LDMX4(a[tm][0], a[tm][1], a[tm][2], a[tm][3], ad);
            }
#pragma unroll
            for (int tp = 0; tp < 2; tp++) {
                uint32_t bd = sbase + (uint32_t)((n0 + tp * 16 + lb_row) * SA2 + k0h + lb_col) * 2;
                LDMX4(b[2 * tp][0], b[2 * tp][1], b[2 * tp + 1][0], b[2 * tp + 1][1], bd);
            }
#pragma unroll
            for (int tm = 0; tm < 4; tm++)
#pragma unroll
                for (int tn = 0; tn < 4; tn++)
                    MMA_F16(acc[tm][tn], a[tm], b[tn]);
        }

        // epilogue
        const int tokbase = (s + 12 * it) * 128;
#pragma unroll
        for (int tm = 0; tm < 4; tm++) {
            const size_t row0 = (size_t)tokbase + m0 + tm * 16 + (lane >> 2);
            float* ob = out + ((size_t)h * ntok + row0) * D_OUTD + dbase + n0 + 2 * (lane & 3);
#pragma unroll
            for (int tn = 0; tn < 4; tn++) {
                float2 v0; v0.x = acc[tm][tn][0]; v0.y = acc[tm][tn][1];
                float2 v1; v1.x = acc[tm][tn][2]; v1.y = acc[tm][tn][3];
                *(float2*)(ob + tn * 8) = v0;
                *(float2*)(ob + tn * 8 + 8 * D_OUTD) = v1;
            }
        }
    }
}

// ---------------------------------------------------------------------------
extern "C" void kernel_launch(void* const* d_in, const int* in_sizes, int n_in,
                              void* d_out, int out_size)
{
    const float* x   = (const float*)d_in[0];
    const float* dw  = (const float*)d_in[1];
    const float* db  = (const float*)d_in[2];
    const float* ntl = (const float*)d_in[3];
    const float* lo  = (const float*)d_in[4];
    const float* gw  = (const float*)d_in[5];
    const float* gb  = (const float*)d_in[6];
    float* out = (float*)d_out;

    int ntok = in_sizes[0] / D_IN;   // 8192

    cudaFuncSetAttribute(k1_mma, cudaFuncAttributeMaxDynamicSharedMemorySize, SMEM1);
    cudaFuncSetAttribute(k2_mma, cudaFuncAttributeMaxDynamicSharedMemorySize, SMEM2);

    k_prep<<<NCOL + 288, 256>>>(dw, gw, lo);
    k1_mma<<<ntok / 64, T1, SMEM1>>>(x, db, ntl, gb, ntok);

    dim3 g2(D_OUTD / 128, NHEADS, 12);
    k2_mma<<<g2, T2, SMEM2>>>(out, ntok);
}